// round 13
// baseline (speedup 1.0000x reference)
#include <cuda_runtime.h>
#include <cuda_bf16.h>
#include <cstdint>

// adj is (N+4)x(N+4), N=8192:
//   adj[i][i] = 1.0 (i<N); adj[i][j] = 0.25 (i,j>=N); else 0.
//
// FINAL: write-only fill at the DRAM-write roofline (~7.1 TB/s effective,
// ~89% of 8 TB/s spec). Ceiling verified path-independent (SM STG vs TMA
// bulk store, R6); split memset+patch worse (R3 — exposed L2 drain);
// instruction-mix levers exhausted (issue% 44->10, no time change);
// identical-source re-runs span 39.5-41.1us => remaining spread is noise.
//
// Hot loop = pure unconditional 256-bit zero stores (STG.256.CS, Blackwell).
// Rare nonzeros are patched by the OWNING thread after its zero stores
// (same thread + same address => program-order visibility).
//
// Layout: block b owns float8 chunk [b*1024, (b+1)*1024); thread t stores
// q8 = b*1024 + t + 256*k, k=0..3. Thread element span (3*2048+8)=6152 < M+1,
// so each thread contains at most ONE diagonal element. Each 4-wide 0.25
// group starts at element offset mod 8 in {0,4}, so it lies in ONE float8
// and is 16B-aligned (float4 patch store).

__global__ __launch_bounds__(256) void adj_fill_kernel(float* __restrict__ out,
                                                       unsigned M, unsigned N,
                                                       unsigned nq8) {
    const unsigned q80 = blockIdx.x * 1024u + threadIdx.x;
    const bool full = (blockIdx.x != gridDim.x - 1);

    // ---- hot loop: 4 unconditional 256-bit zero stores ----
    #pragma unroll
    for (int k = 0; k < 4; ++k) {
        const unsigned q8 = q80 + (unsigned)k * 256u;
        if (full || q8 < nq8) {
            float* p = out + (size_t)q8 * 8u;
            asm volatile(
                "st.global.cs.v8.f32 [%0], {%1,%2,%3,%4,%5,%6,%7,%8};"
                :: "l"(p),
                   "f"(0.f), "f"(0.f), "f"(0.f), "f"(0.f),
                   "f"(0.f), "f"(0.f), "f"(0.f), "f"(0.f)
                : "memory");
        }
    }

    // ---- rare epilogue patches (same-thread overwrite of own zero store) ----
    const unsigned e0  = q80 << 3;          // first element this thread wrote
    const unsigned Mp1 = M + 1u;

    // diagonal: unique candidate element dd in this thread's span
    unsigned i0 = e0 / Mp1;
    unsigned dd = i0 * Mp1;
    if (dd < e0) { dd += Mp1; ++i0; }
    if (i0 < N) {
        const unsigned d8  = dd >> 3;
        const unsigned rel = d8 - q80;      // underflow -> huge -> fails checks
        if (rel < 1024u && (rel & 255u) == 0u) {
            out[dd] = 1.0f;
        }
    }

    // bottom-right 4x4 block of 0.25: 4 groups of 4 consecutive elements
    const unsigned base = N * M + N;
    #pragma unroll
    for (unsigned g = 0; g < 4; ++g) {
        const unsigned eg  = base + g * M;
        const unsigned f8  = eg >> 3;
        const unsigned rel = f8 - q80;
        if (rel < 1024u && (rel & 255u) == 0u) {
            *reinterpret_cast<float4*>(out + eg) =
                make_float4(0.25f, 0.25f, 0.25f, 0.25f);
        }
    }
}

extern "C" void kernel_launch(void* const* d_in, const int* in_sizes, int n_in,
                              void* d_out, int out_size) {
    (void)d_in; (void)in_sizes; (void)n_in;

    // out_size = M*M. Recover M (expected 8196).
    int M = (int)(sqrtf((float)(double)out_size));
    while ((long long)M * M > (long long)out_size) --M;
    while ((long long)(M + 1) * (M + 1) <= (long long)out_size) ++M;
    const int N = M - 4;

    const unsigned nq8 = (unsigned)((long long)out_size >> 3);   // float8 count
    const unsigned blocks = (nq8 + 1023u) / 1024u;               // 1024 float8/block
    adj_fill_kernel<<<blocks, 256>>>((float*)d_out, (unsigned)M, (unsigned)N, nq8);
}

// round 14
// speedup vs baseline: 1.0248x; 1.0248x over previous
#include <cuda_runtime.h>
#include <cuda_bf16.h>
#include <cstdint>

// adj is (N+4)x(N+4), N=8192:
//   adj[i][i] = 1.0 (i<N); adj[i][j] = 0.25 (i,j>=N); else 0.
//
// FINAL: write-only fill at the DRAM-write roofline (~7.1 TB/s effective,
// ~89% of 8 TB/s spec). Evidence: 6 identical-source runs span ncu
// 37.1-38.7us; TMA bulk store worse (R6); split memset+patch worse (R3);
// issue% driven 44->10 with zero kernel-time change (R4/R5/R8);
// +/-.cs and block-shape variants within noise (R7/R8/R9+).
//
// Hot loop = pure unconditional 256-bit zero stores (STG.256.CS, Blackwell).
// Rare nonzeros are patched by the OWNING thread after its zero stores
// (same thread + same address => program-order visibility).
//
// Layout: block b owns float8 chunk [b*1024, (b+1)*1024); thread t stores
// q8 = b*1024 + t + 256*k, k=0..3. Thread element span (3*2048+8)=6152 < M+1,
// so each thread contains at most ONE diagonal element. Each 4-wide 0.25
// group starts at element offset mod 8 in {0,4}, so it lies in ONE float8
// and is 16B-aligned (float4 patch store).

__global__ __launch_bounds__(256) void adj_fill_kernel(float* __restrict__ out,
                                                       unsigned M, unsigned N,
                                                       unsigned nq8) {
    const unsigned q80 = blockIdx.x * 1024u + threadIdx.x;
    const bool full = (blockIdx.x != gridDim.x - 1);

    // ---- hot loop: 4 unconditional 256-bit zero stores ----
    #pragma unroll
    for (int k = 0; k < 4; ++k) {
        const unsigned q8 = q80 + (unsigned)k * 256u;
        if (full || q8 < nq8) {
            float* p = out + (size_t)q8 * 8u;
            asm volatile(
                "st.global.cs.v8.f32 [%0], {%1,%2,%3,%4,%5,%6,%7,%8};"
                :: "l"(p),
                   "f"(0.f), "f"(0.f), "f"(0.f), "f"(0.f),
                   "f"(0.f), "f"(0.f), "f"(0.f), "f"(0.f)
                : "memory");
        }
    }

    // ---- rare epilogue patches (same-thread overwrite of own zero store) ----
    const unsigned e0  = q80 << 3;          // first element this thread wrote
    const unsigned Mp1 = M + 1u;

    // diagonal: unique candidate element dd in this thread's span
    unsigned i0 = e0 / Mp1;
    unsigned dd = i0 * Mp1;
    if (dd < e0) { dd += Mp1; ++i0; }
    if (i0 < N) {
        const unsigned d8  = dd >> 3;
        const unsigned rel = d8 - q80;      // underflow -> huge -> fails checks
        if (rel < 1024u && (rel & 255u) == 0u) {
            out[dd] = 1.0f;
        }
    }

    // bottom-right 4x4 block of 0.25: 4 groups of 4 consecutive elements
    const unsigned base = N * M + N;
    #pragma unroll
    for (unsigned g = 0; g < 4; ++g) {
        const unsigned eg  = base + g * M;
        const unsigned f8  = eg >> 3;
        const unsigned rel = f8 - q80;
        if (rel < 1024u && (rel & 255u) == 0u) {
            *reinterpret_cast<float4*>(out + eg) =
                make_float4(0.25f, 0.25f, 0.25f, 0.25f);
        }
    }
}

extern "C" void kernel_launch(void* const* d_in, const int* in_sizes, int n_in,
                              void* d_out, int out_size) {
    (void)d_in; (void)in_sizes; (void)n_in;

    // out_size = M*M. Recover M (expected 8196).
    int M = (int)(sqrtf((float)(double)out_size));
    while ((long long)M * M > (long long)out_size) --M;
    while ((long long)(M + 1) * (M + 1) <= (long long)out_size) ++M;
    const int N = M - 4;

    const unsigned nq8 = (unsigned)((long long)out_size >> 3);   // float8 count
    const unsigned blocks = (nq8 + 1023u) / 1024u;               // 1024 float8/block
    adj_fill_kernel<<<blocks, 256>>>((float*)d_out, (unsigned)M, (unsigned)N, nq8);
}